// round 12
// baseline (speedup 1.0000x reference)
#include <cuda_runtime.h>
#include <cstddef>

#define B_   4
#define N_   2048
#define T_   64
#define CI_  32
#define CO_  32
#define K_   6
#define TAU_ 3
#define CHT  16                    /* t's per chunk          */
#define PTT  (CHT + 2)             /* panel t's incl. 2 halo */
#define PW   (PTT * CI_)           /* panel width in j = 576 */

static constexpr size_t    PANEL      = (size_t)N_ * PW;       // 1,179,648 floats
static constexpr long long PLANE_SZ   = (long long)B_ * N_ * T_ * CO_;  // 16,777,216

// Scratch: two ping-pong complex panels, 4 x 4.7 MB = 18.9 MB total.
__device__ __align__(256) float g_Ar[PANEL];
__device__ __align__(256) float g_Ai[PANEL];
__device__ __align__(256) float g_Br[PANEL];
__device__ __align__(256) float g_Bi[PANEL];

// ---------------------------------------------------------------------------
// Load P0 panel for (batch b, chunk starting at t0):
//   panel[n][tt][ci] = x[b][n][t0-2+tt][ci], zeros where t<0 (lag padding).
// ---------------------------------------------------------------------------
__global__ void copy_chunk_kernel(const float* __restrict__ xr,
                                  const float* __restrict__ xi,
                                  int b, int t0)
{
    size_t p = (size_t)blockIdx.x * blockDim.x + threadIdx.x;
    const size_t stride = (size_t)gridDim.x * blockDim.x;
    for (; p < PANEL; p += stride) {
        const int n  = (int)(p / PW);
        const int r  = (int)(p % PW);
        const int tt = r / CI_;
        const int ci = r % CI_;
        const int t  = t0 - 2 + tt;            // may be negative (halo of chunk 0)
        float vr = 0.f, vi = 0.f;
        if (t >= 0) {
            const size_t src = (((size_t)b * N_ + n) * T_ + t) * CI_ + ci;
            vr = xr[src];
            vi = xi[src];
        }
        g_Ar[p] = vr;
        g_Ai[p] = vi;
    }
}

// ---------------------------------------------------------------------------
// One Chebyshev step on a panel:
//   C[n][j] = sum_m G[n][m] * P_prev[m][j]   (complex, j < PW)
//   P_new = C                 (k==1)
//   P_new = 2*C - P_prev2     (k>=2; in-place over prev2's slot: each address
//                              is read-as-Q and written only by the same
//                              thread; the broadly-read P_prev is the other
//                              slot)
// dstIsB: P_new -> slot B (P_prev in A), else the reverse.
// 64x64 tile, BK=16, 256 threads, 4x4 complex per thread. Grid (PW/64, N/64).
// ---------------------------------------------------------------------------
__global__ __launch_bounds__(256) void cheb_gemm_kernel(
    const float* __restrict__ Gr, const float* __restrict__ Gi,
    int dstIsB, int hasPrev2)
{
    float*       Or = dstIsB ? g_Br : g_Ar;
    float*       Oi = dstIsB ? g_Bi : g_Ai;
    const float* Pr = dstIsB ? g_Ar : g_Br;
    const float* Pi = dstIsB ? g_Ai : g_Bi;
    const float* Qr = hasPrev2 ? Or : nullptr;  // prev2 lives where we write
    const float* Qi = hasPrev2 ? Oi : nullptr;

    __shared__ __align__(16) float sGr[16][64];   // [kk][n] (G tile transposed)
    __shared__ __align__(16) float sGi[16][64];
    __shared__ __align__(16) float sPr[16][64];   // [kk][j]
    __shared__ __align__(16) float sPi[16][64];

    const int tid = threadIdx.x;
    const int tx  = tid & 15;
    const int ty  = tid >> 4;
    const int j0  = blockIdx.x << 6;   // 0..512
    const int n0  = blockIdx.y << 6;   // 0..1984

    const int lgr = tid >> 2;          // 0..63 : G tile row (n)
    const int lgc = (tid & 3) << 2;    // 0,4,8,12 : G tile col (m)
    const int lpr = tid >> 4;          // 0..15 : P tile row (m)
    const int lpc = (tid & 15) << 2;   // 0..60 : P tile col (j)

    const float* gRp = Gr + (size_t)(n0 + lgr) * N_ + lgc;
    const float* gIp = Gi + (size_t)(n0 + lgr) * N_ + lgc;
    const float* pRp = Pr + (size_t)lpr * PW + j0 + lpc;
    const float* pIp = Pi + (size_t)lpr * PW + j0 + lpc;

    float accR[4][4], accI[4][4];
#pragma unroll
    for (int u = 0; u < 4; ++u)
#pragma unroll
        for (int v = 0; v < 4; ++v) { accR[u][v] = 0.f; accI[u][v] = 0.f; }

    for (int m0 = 0; m0 < N_; m0 += 16) {
        const float4 ga = *(const float4*)(gRp + m0);
        const float4 gb = *(const float4*)(gIp + m0);
        const float4 pa = *(const float4*)(pRp + (size_t)m0 * PW);
        const float4 pb = *(const float4*)(pIp + (size_t)m0 * PW);

        sGr[lgc + 0][lgr] = ga.x; sGr[lgc + 1][lgr] = ga.y;
        sGr[lgc + 2][lgr] = ga.z; sGr[lgc + 3][lgr] = ga.w;
        sGi[lgc + 0][lgr] = gb.x; sGi[lgc + 1][lgr] = gb.y;
        sGi[lgc + 2][lgr] = gb.z; sGi[lgc + 3][lgr] = gb.w;
        *(float4*)&sPr[lpr][lpc] = pa;
        *(float4*)&sPi[lpr][lpc] = pb;
        __syncthreads();

#pragma unroll
        for (int kk = 0; kk < 16; ++kk) {
            const float4 arv = *(const float4*)&sGr[kk][ty << 2];
            const float4 aiv = *(const float4*)&sGi[kk][ty << 2];
            const float4 brv = *(const float4*)&sPr[kk][tx << 2];
            const float4 biv = *(const float4*)&sPi[kk][tx << 2];
            const float ar[4] = {arv.x, arv.y, arv.z, arv.w};
            const float ai[4] = {aiv.x, aiv.y, aiv.z, aiv.w};
            const float br[4] = {brv.x, brv.y, brv.z, brv.w};
            const float bi[4] = {biv.x, biv.y, biv.z, biv.w};
#pragma unroll
            for (int u = 0; u < 4; ++u)
#pragma unroll
                for (int v = 0; v < 4; ++v) {
                    accR[u][v] = fmaf(ar[u], br[v], accR[u][v]);
                    accR[u][v] = fmaf(-ai[u], bi[v], accR[u][v]);
                    accI[u][v] = fmaf(ar[u], bi[v], accI[u][v]);
                    accI[u][v] = fmaf(ai[u], br[v], accI[u][v]);
                }
        }
        __syncthreads();
    }

#pragma unroll
    for (int u = 0; u < 4; ++u) {
        const size_t off = (size_t)(n0 + (ty << 2) + u) * PW + (j0 + (tx << 2));
        float4 vr = make_float4(accR[u][0], accR[u][1], accR[u][2], accR[u][3]);
        float4 vi = make_float4(accI[u][0], accI[u][1], accI[u][2], accI[u][3]);
        if (Qr) {
            const float4 qr = *(const float4*)(Qr + off);
            const float4 qi = *(const float4*)(Qi + off);
            vr.x = 2.f * vr.x - qr.x; vr.y = 2.f * vr.y - qr.y;
            vr.z = 2.f * vr.z - qr.z; vr.w = 2.f * vr.w - qr.w;
            vi.x = 2.f * vi.x - qi.x; vi.y = 2.f * vi.y - qi.y;
            vi.z = 2.f * vi.z - qi.z; vi.w = 2.f * vi.w - qi.w;
        }
        *(float4*)(Or + off) = vr;
        *(float4*)(Oi + off) = vi;
    }
}

// ---------------------------------------------------------------------------
// Contraction for one (k, batch, chunk):
//   out_real[b,n,t0+lt,o] (+)= sum_{tau,i} panel[n, lt+2-tau, i] * W[k,tau,i,o]
// OUTPUT LAYOUT (R12 experiment): PLANAR — real plane [0, 16.7M), imag plane
// [16.7M, 33.5M). Interleaved (re,im) is RULED OUT: both input orderings gave
// rel_err = sqrt(2) with it, so whichever order was right still decorrelated.
// Writes remain clamped by out_size (also covers a real-only 16.7M buffer).
// ---------------------------------------------------------------------------
__global__ __launch_bounds__(256) void contract_acc_kernel(
    const float* __restrict__ Wr, const float* __restrict__ Wi,
    const float* __restrict__ biasR, const float* __restrict__ biasI,
    float* __restrict__ out, long long out_sz,
    int srcIsB, int k, int b, int t0, int init)
{
    __shared__ __align__(16) float WsR[TAU_ * CI_ * CO_];
    __shared__ __align__(16) float WsI[TAU_ * CI_ * CO_];
    __shared__ __align__(16) float PsR[PW];
    __shared__ __align__(16) float PsI[PW];

    const int n   = blockIdx.x;
    const int tid = threadIdx.x;
    const int o   = tid & 31;
    const int w   = tid >> 5;            // 8 warps x 2 t's = 16 t's

    const float* pR  = (srcIsB ? g_Br : g_Ar) + (size_t)n * PW;
    const float* pI  = (srcIsB ? g_Bi : g_Ai) + (size_t)n * PW;
    const float* wRk = Wr + k * (TAU_ * CI_ * CO_);
    const float* wIk = Wi + k * (TAU_ * CI_ * CO_);

    for (int idx = tid; idx < PW; idx += 256) {
        PsR[idx] = pR[idx];
        PsI[idx] = pI[idx];
    }
    for (int idx = tid; idx < TAU_ * CI_ * CO_; idx += 256) {
        WsR[idx] = wRk[idx];
        WsI[idx] = wIk[idx];
    }
    __syncthreads();

    float accR[2], accI[2];
    if (init) {
        const float bR = biasR ? biasR[o] : 0.f;
        const float bI = biasI ? biasI[o] : 0.f;
        accR[0] = accR[1] = bR;
        accI[0] = accI[1] = bI;
    } else {
        accR[0] = accR[1] = 0.f;
        accI[0] = accI[1] = 0.f;
    }

    for (int tau = 0; tau < TAU_; ++tau) {
#pragma unroll 4
        for (int i = 0; i < CI_; ++i) {
            const float wr = WsR[(tau * CI_ + i) * CO_ + o];
            const float wi = WsI[(tau * CI_ + i) * CO_ + o];
#pragma unroll
            for (int u = 0; u < 2; ++u) {
                const int lt = (w << 1) + u;          // 0..15
                const int tt = lt + 2 - tau;          // 0..17, always >= 0
                const float prv = PsR[tt * CI_ + i];
                const float piv = PsI[tt * CI_ + i];
                accR[u] = fmaf(prv, wr, accR[u]);
                accR[u] = fmaf(-piv, wi, accR[u]);
                accI[u] = fmaf(prv, wi, accI[u]);
                accI[u] = fmaf(piv, wr, accI[u]);
            }
        }
    }

#pragma unroll
    for (int u = 0; u < 2; ++u) {
        const int t = t0 + (w << 1) + u;
        const long long ridx = (((long long)b * N_ + n) * T_ + t) * CO_ + o;
        const long long iidx = ridx + PLANE_SZ;   // imag plane
        if (init) {
            if (ridx < out_sz) out[ridx] = accR[u];
            if (iidx < out_sz) out[iidx] = accI[u];
        } else {
            if (ridx < out_sz) out[ridx] += accR[u];
            if (iidx < out_sz) out[iidx] += accI[u];
        }
    }
}

// ---------------------------------------------------------------------------
// Host launch. Inputs identified by ELEMENT COUNT, REAL FIRST within each
// size pair (dict insertion order of setup_inputs: x_real, x_imag, gso_real,
// ... — R9/R11 showed input order is NOT the cause of the sqrt(2) error, so
// we keep the high-prior dict order and fix the OUTPUT layout instead).
// ---------------------------------------------------------------------------
extern "C" void kernel_launch(void* const* d_in, const int* in_sizes, int n_in,
                              void* d_out, int out_size)
{
    const float *xr = nullptr, *xi = nullptr;
    const float *gr = nullptr, *gi = nullptr;
    const float *wr = nullptr, *wi = nullptr;
    const float *br = nullptr, *bi = nullptr;

    for (int idx = 0; idx < n_in; ++idx) {
        const float* p = (const float*)d_in[idx];
        switch (in_sizes[idx]) {
            case 16777216: if (!xr) xr = p; else xi = p; break;  // real first
            case 4194304:  if (!gr) gr = p; else gi = p; break;  // real first
            case 18432:    if (!wr) wr = p; else wi = p; break;  // real first
            case 32:       if (!br) br = p; else bi = p; break;  // real first
            default: break;
        }
    }
    if (!xr || !xi || !gr || !gi || !wr || !wi) return;  // cannot identify inputs

    float* out = (float*)d_out;
    const long long out_sz = (long long)out_size;
    const dim3 ggrid(PW / 64, N_ / 64, 1);   // (9, 32)

    for (int b = 0; b < B_; ++b) {
        for (int c = 0; c < T_ / CHT; ++c) {
            const int t0 = c * CHT;
            copy_chunk_kernel<<<1024, 256>>>(xr, xi, b, t0);
            contract_acc_kernel<<<N_, 256>>>(wr, wi, br, bi, out, out_sz,
                                             /*srcIsB=*/0, /*k=*/0, b, t0,
                                             /*init=*/1);
            for (int k = 1; k < K_; ++k) {
                const int dstIsB = k & 1;    // P1->B, P2->A(in-place), P3->B, ...
                cheb_gemm_kernel<<<ggrid, 256>>>(gr, gi, dstIsB,
                                                 /*hasPrev2=*/(k >= 2) ? 1 : 0);
                contract_acc_kernel<<<N_, 256>>>(wr, wi, br, bi, out, out_sz,
                                                 dstIsB, k, b, t0, /*init=*/0);
            }
        }
    }
}

// round 17
// speedup vs baseline: 1.4593x; 1.4593x over previous
#include <cuda_runtime.h>
#include <cuda_bf16.h>
#include <cstdint>
#include <cstddef>

#define B_   4
#define N_   2048
#define T_   64
#define CI_  32
#define CO_  32
#define K_   6
#define TAU_ 3
#define CHT  16                    /* t's per chunk          */
#define PTT  (CHT + 2)             /* panel t's incl. 2 halo */
#define PW   (PTT * CI_)           /* panel width in j = 576 */
#define KC   32                    /* bf16 k per mainloop chunk */
#define AP   80                    /* smem row pitch (bytes), conflict-free */

static constexpr size_t    PANEL    = (size_t)N_ * PW;                 // floats
static constexpr long long PLANE_SZ = (long long)B_ * N_ * T_ * CO_;   // 16,777,216

// Scratch: two ping-pong complex panels, 4 x 4.7 MB = 18.9 MB (proven-safe size).
__device__ __align__(256) float g_Ar[PANEL];
__device__ __align__(256) float g_Ai[PANEL];
__device__ __align__(256) float g_Br[PANEL];
__device__ __align__(256) float g_Bi[PANEL];

// Dynamic smem plane offsets (A: 128 rows x 80B, B: 64 rows x 80B)
#define SM_ARH  0
#define SM_ARL  10240
#define SM_AIH  20480
#define SM_AIL  30720
#define SM_BRH  40960
#define SM_BRL  46080
#define SM_BIH  51200
#define SM_BIL  56320
#define SMEM_MM 61440

__device__ __forceinline__ uint32_t smem_u32(const void* p) {
    uint32_t a;
    asm("{ .reg .u64 t; cvta.to.shared.u64 t, %1; cvt.u32.u64 %0, t; }"
        : "=r"(a) : "l"(p));
    return a;
}
__device__ __forceinline__ void ldm_x4(uint32_t* r, uint32_t addr) {
    asm volatile("ldmatrix.sync.aligned.m8n8.x4.shared.b16 {%0,%1,%2,%3}, [%4];"
                 : "=r"(r[0]), "=r"(r[1]), "=r"(r[2]), "=r"(r[3]) : "r"(addr));
}
__device__ __forceinline__ void ldm_x2(uint32_t* r, uint32_t addr) {
    asm volatile("ldmatrix.sync.aligned.m8n8.x2.shared.b16 {%0,%1}, [%2];"
                 : "=r"(r[0]), "=r"(r[1]) : "r"(addr));
}
__device__ __forceinline__ void mma_bf16(float* d, const uint32_t* a,
                                         const uint32_t* b) {
    asm volatile(
        "mma.sync.aligned.m16n8k16.row.col.f32.bf16.bf16.f32 "
        "{%0,%1,%2,%3}, {%4,%5,%6,%7}, {%8,%9}, {%0,%1,%2,%3};"
        : "+f"(d[0]), "+f"(d[1]), "+f"(d[2]), "+f"(d[3])
        : "r"(a[0]), "r"(a[1]), "r"(a[2]), "r"(a[3]), "r"(b[0]), "r"(b[1]));
}

// ---------------------------------------------------------------------------
// Load P0 panel for (batch b, chunk t0): panel[n][tt][ci] = x[b][n][t0-2+tt][ci]
// ---------------------------------------------------------------------------
__global__ void copy_chunk_kernel(const float* __restrict__ xr,
                                  const float* __restrict__ xi,
                                  int b, int t0)
{
    size_t p = (size_t)blockIdx.x * blockDim.x + threadIdx.x;
    const size_t stride = (size_t)gridDim.x * blockDim.x;
    for (; p < PANEL; p += stride) {
        const int n  = (int)(p / PW);
        const int r  = (int)(p % PW);
        const int tt = r / CI_;
        const int ci = r % CI_;
        const int t  = t0 - 2 + tt;
        float vr = 0.f, vi = 0.f;
        if (t >= 0) {
            const size_t src = (((size_t)b * N_ + n) * T_ + t) * CI_ + ci;
            vr = xr[src];
            vi = xi[src];
        }
        g_Ar[p] = vr;
        g_Ai[p] = vi;
    }
}

// ---------------------------------------------------------------------------
// Chebyshev step via warp-level bf16 MMA (portable mma.sync, HMMA pipe):
//   C[n][j] = sum_m G[n][m] * P_prev[m][j]   (complex, fp32 accumulate)
// Precision: hi/lo bf16 split, 3 terms per real product (hh, lh, hl).
// acc0=Gr*Pr, acc1=Gi*Pi, acc2=Gr*Pi+Gi*Pr;  Cr=acc0-acc1, Ci=acc2.
// P_new = C (first step) or 2*C - P_prev2 (in-place over dst slot).
// Grid (PW/64=9, N/128=16), 256 threads = 8 warps (4 m x 2 j), warp = 32x32.
// ---------------------------------------------------------------------------
__global__ __launch_bounds__(256, 1) void cheb_gemm_mma_kernel(
    const float* __restrict__ Gr, const float* __restrict__ Gi,
    int dstIsB, int hasPrev2)
{
    extern __shared__ char smem[];
    const uint32_t sb = smem_u32(smem);

    float*       Or = dstIsB ? g_Br : g_Ar;
    float*       Oi = dstIsB ? g_Bi : g_Ai;
    const float* Pr = dstIsB ? g_Ar : g_Br;
    const float* Pi = dstIsB ? g_Ai : g_Bi;

    const int tid  = threadIdx.x;
    const int lane = tid & 31;
    const int wid  = tid >> 5;
    const int wm   = (wid & 3) << 5;        // warp m offset 0..96
    const int wn   = (wid >> 2) << 5;       // warp j offset 0 or 32
    const int j0   = blockIdx.x << 6;       // 0..512
    const int n0   = blockIdx.y << 7;       // 0..1920

    float acc0[2][4][4], acc1[2][4][4], acc2[2][4][4];
#pragma unroll
    for (int mt = 0; mt < 2; ++mt)
#pragma unroll
        for (int nt = 0; nt < 4; ++nt)
#pragma unroll
            for (int e = 0; e < 4; ++e) {
                acc0[mt][nt][e] = 0.f;
                acc1[mt][nt][e] = 0.f;
                acc2[mt][nt][e] = 0.f;
            }

    // precomputed ldmatrix lane addresses (offsets within plane)
    const int aRow = lane & 15;             // + mtile base
    const int aSeg = lane >> 4;             // + 2*kt
    const int l2   = lane & 15;
    const int bRow = l2 & 7;                // + ntile base
    const int bSeg = l2 >> 3;               // + 2*kt

    for (int m0 = 0; m0 < N_; m0 += KC) {
        __syncthreads();

        // ---- A loader: G[128 x KC] fp32 x2 -> 4 bf16 planes (hi/lo, r/i) ----
        {
            const int r  = tid >> 1;             // 0..127
            const int f0 = (tid & 1) * 4;        // float4 index base (0 or 4)
            const float* gR = Gr + (size_t)(n0 + r) * N_ + m0;
            const float* gI = Gi + (size_t)(n0 + r) * N_ + m0;
#pragma unroll
            for (int fi = 0; fi < 4; ++fi) {
                const int f = f0 + fi;           // 0..7 (8 float4 per row)
                const uint32_t soff = (uint32_t)(r * AP + f * 8);
                {
                    const float4 v = *(const float4*)(gR + f * 4);
                    const __nv_bfloat16 h0 = __float2bfloat16(v.x);
                    const __nv_bfloat16 h1 = __float2bfloat16(v.y);
                    const __nv_bfloat16 h2 = __float2bfloat16(v.z);
                    const __nv_bfloat16 h3 = __float2bfloat16(v.w);
                    *(__nv_bfloat162*)(smem + SM_ARH + soff)     = __halves2bfloat162(h0, h1);
                    *(__nv_bfloat162*)(smem + SM_ARH + soff + 4) = __halves2bfloat162(h2, h3);
                    *(__nv_bfloat162*)(smem + SM_ARL + soff)     = __halves2bfloat162(
                        __float2bfloat16(v.x - __bfloat162float(h0)),
                        __float2bfloat16(v.y - __bfloat162float(h1)));
                    *(__nv_bfloat162*)(smem + SM_ARL + soff + 4) = __halves2bfloat162(
                        __float2bfloat16(v.z - __bfloat162float(h2)),
                        __float2bfloat16(v.w - __bfloat162float(h3)));
                }
                {
                    const float4 v = *(const float4*)(gI + f * 4);
                    const __nv_bfloat16 h0 = __float2bfloat16(v.x);
                    const __nv_bfloat16 h1 = __float2bfloat16(v.y);
                    const __nv_bfloat16 h2 = __float2bfloat16(v.z);
                    const __nv_bfloat16 h3 = __float2bfloat16(v.w);
                    *(__nv_bfloat162*)(smem + SM_AIH + soff)     = __halves2bfloat162(h0, h1);
                    *(__nv_bfloat162*)(smem + SM_AIH + soff + 4) = __halves2bfloat162(h2, h3);
                    *(__nv_bfloat162*)(smem + SM_AIL + soff)     = __halves2bfloat162(
                        __float2bfloat16(v.x - __bfloat162float(h0)),
                        __float2bfloat16(v.y - __bfloat162float(h1)));
                    *(__nv_bfloat162*)(smem + SM_AIL + soff + 4) = __halves2bfloat162(
                        __float2bfloat16(v.z - __bfloat162float(h2)),
                        __float2bfloat16(v.w - __bfloat162float(h3)));
                }
            }
        }
        // ---- B loader: P[KC m x 64 j] -> transposed [j][m] bf16 planes ----
        {
            const int m  = tid >> 3;             // 0..31
            const int jg = tid & 7;              // 0..7 -> 8 j's per thread
            const float* pR = Pr + (size_t)(m0 + m) * PW + j0 + jg * 8;
            const float* pI = Pi + (size_t)(m0 + m) * PW + j0 + jg * 8;
#pragma unroll
            for (int q = 0; q < 2; ++q) {
                const float4 vr4 = *(const float4*)(pR + q * 4);
                const float4 vi4 = *(const float4*)(pI + q * 4);
                const float vr[4] = {vr4.x, vr4.y, vr4.z, vr4.w};
                const float vi[4] = {vi4.x, vi4.y, vi4.z, vi4.w};
#pragma unroll
                for (int e = 0; e < 4; ++e) {
                    const int j = jg * 8 + q * 4 + e;
                    const uint32_t soff = (uint32_t)(j * AP + m * 2);
                    const __nv_bfloat16 hr = __float2bfloat16(vr[e]);
                    const __nv_bfloat16 hi = __float2bfloat16(vi[e]);
                    *(__nv_bfloat16*)(smem + SM_BRH + soff) = hr;
                    *(__nv_bfloat16*)(smem + SM_BIH + soff) = hi;
                    *(__nv_bfloat16*)(smem + SM_BRL + soff) =
                        __float2bfloat16(vr[e] - __bfloat162float(hr));
                    *(__nv_bfloat16*)(smem + SM_BIL + soff) =
                        __float2bfloat16(vi[e] - __bfloat162float(hi));
                }
            }
        }
        __syncthreads();

        // ---- compute: 2 k16 tiles per chunk ----
#pragma unroll
        for (int kt = 0; kt < 2; ++kt) {
            uint32_t Af[4][2][4];   // plane (rh,rl,ih,il), mtile, regs
            uint32_t Bf[4][4][2];   // plane (prh,prl,pih,pil), ntile, regs
            const uint32_t aBase[4] = {SM_ARH, SM_ARL, SM_AIH, SM_AIL};
            const uint32_t bBase[4] = {SM_BRH, SM_BRL, SM_BIH, SM_BIL};
#pragma unroll
            for (int p = 0; p < 4; ++p) {
#pragma unroll
                for (int mt = 0; mt < 2; ++mt) {
                    const int row = wm + mt * 16 + aRow;
                    const int seg = kt * 2 + aSeg;
                    ldm_x4(Af[p][mt], sb + aBase[p] + row * AP + seg * 16);
                }
#pragma unroll
                for (int nt = 0; nt < 4; ++nt) {
                    const int row = wn + nt * 8 + bRow;
                    const int seg = kt * 2 + bSeg;
                    ldm_x2(Bf[p][nt], sb + bBase[p] + row * AP + seg * 16);
                }
            }
#pragma unroll
            for (int mt = 0; mt < 2; ++mt)
#pragma unroll
                for (int nt = 0; nt < 4; ++nt) {
                    // acc0 = Gr*Pr : hh, lh, hl
                    mma_bf16(acc0[mt][nt], Af[0][mt], Bf[0][nt]);
                    mma_bf16(acc0[mt][nt], Af[1][mt], Bf[0][nt]);
                    mma_bf16(acc0[mt][nt], Af[0][mt], Bf[1][nt]);
                    // acc1 = Gi*Pi
                    mma_bf16(acc1[mt][nt], Af[2][mt], Bf[2][nt]);
                    mma_bf16(acc1[mt][nt], Af[3][mt], Bf[2][nt]);
                    mma_bf16(acc1[mt][nt], Af[2][mt], Bf[3][nt]);
                    // acc2 = Gr*Pi + Gi*Pr
                    mma_bf16(acc2[mt][nt], Af[0][mt], Bf[2][nt]);
                    mma_bf16(acc2[mt][nt], Af[1][mt], Bf[2][nt]);
                    mma_bf16(acc2[mt][nt], Af[0][mt], Bf[3][nt]);
                    mma_bf16(acc2[mt][nt], Af[2][mt], Bf[0][nt]);
                    mma_bf16(acc2[mt][nt], Af[3][mt], Bf[0][nt]);
                    mma_bf16(acc2[mt][nt], Af[2][mt], Bf[1][nt]);
                }
        }
    }

    // ---- epilogue: Cr = acc0-acc1, Ci = acc2; P_new = C or 2C - Q (in place)
    const int g  = lane >> 2;
    const int tg = lane & 3;
#pragma unroll
    for (int mt = 0; mt < 2; ++mt)
#pragma unroll
        for (int nt = 0; nt < 4; ++nt) {
            const int col = j0 + wn + nt * 8 + 2 * tg;
#pragma unroll
            for (int h = 0; h < 2; ++h) {          // d0/d1 vs d2/d3 rows
                const int row = n0 + wm + mt * 16 + g + h * 8;
                const size_t idx = (size_t)row * PW + col;
                float cr0 = acc0[mt][nt][h * 2 + 0] - acc1[mt][nt][h * 2 + 0];
                float cr1 = acc0[mt][nt][h * 2 + 1] - acc1[mt][nt][h * 2 + 1];
                float ci0 = acc2[mt][nt][h * 2 + 0];
                float ci1 = acc2[mt][nt][h * 2 + 1];
                if (hasPrev2) {
                    const float2 qr = *(const float2*)(Or + idx);
                    const float2 qi = *(const float2*)(Oi + idx);
                    cr0 = 2.f * cr0 - qr.x;  cr1 = 2.f * cr1 - qr.y;
                    ci0 = 2.f * ci0 - qi.x;  ci1 = 2.f * ci1 - qi.y;
                }
                *(float2*)(Or + idx) = make_float2(cr0, cr1);
                *(float2*)(Oi + idx) = make_float2(ci0, ci1);
            }
        }
}

// ---------------------------------------------------------------------------
// Contraction for one (k, batch, chunk) — unchanged from the passing R12.
// Output PLANAR: real plane [0, 16.7M), imag plane [16.7M, 33.5M).
// ---------------------------------------------------------------------------
__global__ __launch_bounds__(256) void contract_acc_kernel(
    const float* __restrict__ Wr, const float* __restrict__ Wi,
    const float* __restrict__ biasR, const float* __restrict__ biasI,
    float* __restrict__ out, long long out_sz,
    int srcIsB, int k, int b, int t0, int init)
{
    __shared__ __align__(16) float WsR[TAU_ * CI_ * CO_];
    __shared__ __align__(16) float WsI[TAU_ * CI_ * CO_];
    __shared__ __align__(16) float PsR[PW];
    __shared__ __align__(16) float PsI[PW];

    const int n   = blockIdx.x;
    const int tid = threadIdx.x;
    const int o   = tid & 31;
    const int w   = tid >> 5;

    const float* pR  = (srcIsB ? g_Br : g_Ar) + (size_t)n * PW;
    const float* pI  = (srcIsB ? g_Bi : g_Ai) + (size_t)n * PW;
    const float* wRk = Wr + k * (TAU_ * CI_ * CO_);
    const float* wIk = Wi + k * (TAU_ * CI_ * CO_);

    for (int idx = tid; idx < PW; idx += 256) {
        PsR[idx] = pR[idx];
        PsI[idx] = pI[idx];
    }
    for (int idx = tid; idx < TAU_ * CI_ * CO_; idx += 256) {
        WsR[idx] = wRk[idx];
        WsI[idx] = wIk[idx];
    }
    __syncthreads();

    float accR[2], accI[2];
    if (init) {
        const float bR = biasR ? biasR[o] : 0.f;
        const float bI = biasI ? biasI[o] : 0.f;
        accR[0] = accR[1] = bR;
        accI[0] = accI[1] = bI;
    } else {
        accR[0] = accR[1] = 0.f;
        accI[0] = accI[1] = 0.f;
    }

    for (int tau = 0; tau < TAU_; ++tau) {
#pragma unroll 4
        for (int i = 0; i < CI_; ++i) {
            const float wr = WsR[(tau * CI_ + i) * CO_ + o];
            const float wi = WsI[(tau * CI_ + i) * CO_ + o];
#pragma unroll
            for (int u = 0; u < 2; ++u) {
                const int lt = (w << 1) + u;
                const int tt = lt + 2 - tau;
                const float prv = PsR[tt * CI_ + i];
                const float piv = PsI[tt * CI_ + i];
                accR[u] = fmaf(prv, wr, accR[u]);
                accR[u] = fmaf(-piv, wi, accR[u]);
                accI[u] = fmaf(prv, wi, accI[u]);
                accI[u] = fmaf(piv, wr, accI[u]);
            }
        }
    }

#pragma unroll
    for (int u = 0; u < 2; ++u) {
        const int t = t0 + (w << 1) + u;
        const long long ridx = (((long long)b * N_ + n) * T_ + t) * CO_ + o;
        const long long iidx = ridx + PLANE_SZ;
        if (init) {
            if (ridx < out_sz) out[ridx] = accR[u];
            if (iidx < out_sz) out[iidx] = accI[u];
        } else {
            if (ridx < out_sz) out[ridx] += accR[u];
            if (iidx < out_sz) out[iidx] += accI[u];
        }
    }
}

// ---------------------------------------------------------------------------
// Host launch: proven R12 structure; SIMT GEMM replaced by bf16 mma.sync GEMM.
// ---------------------------------------------------------------------------
extern "C" void kernel_launch(void* const* d_in, const int* in_sizes, int n_in,
                              void* d_out, int out_size)
{
    const float *xr = nullptr, *xi = nullptr;
    const float *gr = nullptr, *gi = nullptr;
    const float *wr = nullptr, *wi = nullptr;
    const float *br = nullptr, *bi = nullptr;

    for (int idx = 0; idx < n_in; ++idx) {
        const float* p = (const float*)d_in[idx];
        switch (in_sizes[idx]) {
            case 16777216: if (!xr) xr = p; else xi = p; break;  // real first
            case 4194304:  if (!gr) gr = p; else gi = p; break;
            case 18432:    if (!wr) wr = p; else wi = p; break;
            case 32:       if (!br) br = p; else bi = p; break;
            default: break;
        }
    }
    if (!xr || !xi || !gr || !gi || !wr || !wi) return;

    (void)cudaFuncSetAttribute(cheb_gemm_mma_kernel,
                               cudaFuncAttributeMaxDynamicSharedMemorySize,
                               SMEM_MM);

    float* out = (float*)d_out;
    const long long out_sz = (long long)out_size;
    const dim3 ggrid(PW / 64, N_ / 128, 1);   // (9, 16)

    for (int b = 0; b < B_; ++b) {
        for (int c = 0; c < T_ / CHT; ++c) {
            const int t0 = c * CHT;
            copy_chunk_kernel<<<1024, 256>>>(xr, xi, b, t0);
            contract_acc_kernel<<<N_, 256>>>(wr, wi, br, bi, out, out_sz,
                                             /*srcIsB=*/0, /*k=*/0, b, t0,
                                             /*init=*/1);
            for (int k = 1; k < K_; ++k) {
                const int dstIsB = k & 1;
                cheb_gemm_mma_kernel<<<ggrid, 256, SMEM_MM>>>(
                    gr, gi, dstIsB, /*hasPrev2=*/(k >= 2) ? 1 : 0);
                contract_acc_kernel<<<N_, 256>>>(wr, wi, br, bi, out, out_sz,
                                                 dstIsB, k, b, t0, /*init=*/0);
            }
        }
    }
}